// round 3
// baseline (speedup 1.0000x reference)
#include <cuda_runtime.h>

// ButterflyTransform: x[8192,4096] fp32, W[12,2048,2,2] fp32.
// All 12 layers use identical adjacent pairing -> per pair n the whole network
// is one composed 2x2 matrix M[n] = W0[n]@...@W11[n] (row-vector y = x*W).
//
// Single fused kernel: each thread composes its own 2 matrices from W
// (L2-resident, 384 KB) in a prologue, then streams 16 rows of x.
// No second kernel, no device-scratch round trip, no inter-kernel gap.

#define BATCH   8192
#define SIZE    4096
#define NPAIRS  (SIZE / 2)        // 2048
#define LOG_N   12
#define F4_PER_ROW (SIZE / 4)     // 1024 float4 per row

#define TPB     256
#define ROWS    16                // rows per block
#define STRIPS  (F4_PER_ROW / TPB)     // 4 column strips
#define ROWBLKS (BATCH / ROWS)         // 512

__global__ void __launch_bounds__(TPB, 8)
fused_kernel(const float* __restrict__ x,
             const float* __restrict__ W,
             float* __restrict__ out) {
    const int col4 = blockIdx.x * TPB + threadIdx.x;   // 0..1023 (float4 column)

    // ---- compose prologue: M = W0 @ W1 @ ... @ W11 for this thread's 2 pairs ----
    const float4* __restrict__ Wl = reinterpret_cast<const float4*>(W);  // [l][pair]
    const int pA = 2 * col4;
    float4 mA = Wl[pA];
    float4 mB = Wl[pA + 1];
#pragma unroll
    for (int l = 1; l < LOG_N; l++) {
        float4 w = Wl[l * NPAIRS + pA];
        float4 t;
        t.x = fmaf(mA.x, w.x, mA.y * w.z);
        t.y = fmaf(mA.x, w.y, mA.y * w.w);
        t.z = fmaf(mA.z, w.x, mA.w * w.z);
        t.w = fmaf(mA.z, w.y, mA.w * w.w);
        mA = t;
        w = Wl[l * NPAIRS + pA + 1];
        t.x = fmaf(mB.x, w.x, mB.y * w.z);
        t.y = fmaf(mB.x, w.y, mB.y * w.w);
        t.z = fmaf(mB.z, w.x, mB.w * w.z);
        t.w = fmaf(mB.z, w.y, mB.w * w.w);
        mB = t;
    }

    // ---- streaming apply: 16 rows, touch-once loads/stores ----
    const float4* __restrict__ xin  = reinterpret_cast<const float4*>(x);
    float4* __restrict__       yout = reinterpret_cast<float4*>(out);

    long base = (long)blockIdx.y * ROWS * F4_PER_ROW + col4;
#pragma unroll
    for (int r = 0; r < ROWS; r++) {
        long idx = base + (long)r * F4_PER_ROW;
        float4 v = __ldcs(&xin[idx]);
        float4 o;
        o.x = fmaf(v.x, mA.x, v.y * mA.z);
        o.y = fmaf(v.x, mA.y, v.y * mA.w);
        o.z = fmaf(v.z, mB.x, v.w * mB.z);
        o.w = fmaf(v.z, mB.y, v.w * mB.w);
        __stcs(&yout[idx], o);
    }
}

extern "C" void kernel_launch(void* const* d_in, const int* in_sizes, int n_in,
                              void* d_out, int out_size) {
    const float* x = (const float*)d_in[0];   // [8192, 4096]
    const float* W = (const float*)d_in[1];   // [12, 2048, 2, 2]
    float* out = (float*)d_out;

    dim3 grid(STRIPS, ROWBLKS);               // (4, 512) = 2048 blocks
    fused_kernel<<<grid, TPB>>>(x, W, out);
}

// round 6
// speedup vs baseline: 1.0801x; 1.0801x over previous
#include <cuda_runtime.h>

// ButterflyTransform: x[8192,4096] fp32, W[12,2048,2,2] fp32.
// All 12 layers use identical adjacent pairing -> per pair n the whole network
// is one composed 2x2 matrix M[n] = W0[n]@...@W11[n] (row-vector y = x*W).
// Phase 1: compose 2048 matrices. All 12 W loads are hoisted (MLP=12) so the
// kernel is one DRAM round-trip, not a 12-deep latency chain.
// Phase 2: streaming apply (exact R1 kernel: 37.7us, 72% DRAM).

#define BATCH   8192
#define SIZE    4096
#define NPAIRS  (SIZE / 2)        // 2048
#define LOG_N   12
#define F4_PER_ROW (SIZE / 4)     // 1024 float4 per row

// Composed matrices: (m00, m01, m10, m11) per pair. 32 KB scratch.
__device__ float4 g_M[NPAIRS];

__global__ void compose_kernel(const float* __restrict__ W) {
    int n = blockIdx.x * blockDim.x + threadIdx.x;
    if (n >= NPAIRS) return;
    const float4* __restrict__ Wl = reinterpret_cast<const float4*>(W);  // [l][pair]

    // Hoist all 12 loads: independent, batched -> one DRAM latency exposure.
    float4 w[LOG_N];
#pragma unroll
    for (int l = 0; l < LOG_N; l++)
        w[l] = Wl[l * NPAIRS + n];

    float4 m = w[0];
#pragma unroll
    for (int l = 1; l < LOG_N; l++) {
        // M_new = M @ W_l  (row-vector composition)
        float4 t;
        t.x = fmaf(m.x, w[l].x, m.y * w[l].z);
        t.y = fmaf(m.x, w[l].y, m.y * w[l].w);
        t.z = fmaf(m.z, w[l].x, m.w * w[l].z);
        t.w = fmaf(m.z, w[l].y, m.w * w[l].w);
        m = t;
    }
    g_M[n] = m;
}

#define ROWS_PER_BLOCK 16
#define TPB 256

__global__ void __launch_bounds__(TPB) apply_kernel(const float* __restrict__ x,
                                                    float* __restrict__ out) {
    // Each thread owns one float4 column slot (2 pairs) and walks ROWS_PER_BLOCK rows,
    // keeping its two composed matrices in registers.
    int col4 = blockIdx.x * TPB + threadIdx.x;        // 0..1023
    float4 mA = g_M[2 * col4];
    float4 mB = g_M[2 * col4 + 1];

    const float4* __restrict__ xin  = reinterpret_cast<const float4*>(x);
    float4* __restrict__       yout = reinterpret_cast<float4*>(out);

    int row0 = blockIdx.y * ROWS_PER_BLOCK;
    long base = (long)row0 * F4_PER_ROW + col4;

#pragma unroll
    for (int r = 0; r < ROWS_PER_BLOCK; r++) {
        long idx = base + (long)r * F4_PER_ROW;
        float4 v = xin[idx];
        float4 o;
        // y_j = sum_i x_i * M[i][j]
        o.x = fmaf(v.x, mA.x, v.y * mA.z);
        o.y = fmaf(v.x, mA.y, v.y * mA.w);
        o.z = fmaf(v.z, mB.x, v.w * mB.z);
        o.w = fmaf(v.z, mB.y, v.w * mB.w);
        yout[idx] = o;
    }
}

extern "C" void kernel_launch(void* const* d_in, const int* in_sizes, int n_in,
                              void* d_out, int out_size) {
    const float* x = (const float*)d_in[0];   // [8192, 4096]
    const float* W = (const float*)d_in[1];   // [12, 2048, 2, 2]
    float* out = (float*)d_out;

    compose_kernel<<<32, 64>>>(W);            // 2048 threads over 32 blocks

    dim3 grid(F4_PER_ROW / TPB, BATCH / ROWS_PER_BLOCK);  // (4, 512)
    apply_kernel<<<grid, TPB>>>(x, out);
}